// round 12
// baseline (speedup 1.0000x reference)
#include <cuda_runtime.h>
#include <cuda_bf16.h>
#include <cuda_fp16.h>
#include <math.h>
#include <stdint.h>

// Problem constants (GCNN_85409719648958): B=8, N=2000, E=64000, F=1024, D=128
#define NB     16      // 2 branches x 8 batches
#define NNODE  2000
#define NPAD   2048    // padded node count
#define NEDGE  64000
#define FDIM   1024
#define DDIM   128

#define WSCALE 16.0f   // W pre-scale for e4m3 (avoids subnormals); undone in epilogue

// ---------------- scratch (device globals; no runtime allocation) ----------
__device__ uint8_t g_Xq [(size_t)NB * NPAD * FDIM];   // 32 MB X in e4m3 (padded rows zero)
__device__ uint8_t g_Wq [(size_t)2 * FDIM * FDIM];    // 2 MB  (Wg^T * 16) in e4m3, K-major
__device__ uint8_t g_H  [(size_t)NB * NPAD * FDIM];   // 32 MB H = X@Wg, node-major e4m3
__device__ int   g_degi[NB * NNODE];                  // edge in-degree (no self loop)
__device__ float g_dinv[NB * NNODE];
__device__ int   g_rowptr[NB * NPAD];                 // CSR row offsets (by target)
__device__ int   g_cur[NB * NNODE];                   // fill cursors
__device__ int   g_csr_src[NB * NEDGE];
__device__ float g_csr_w  [NB * NEDGE];
__device__ float g_gmean[NB * FDIM];                  // mean_n leaky(A@H + b)
__device__ float g_gf[NB * DDIM];                     // leaky(g @ Wf + bf)

// ---------------- small helpers ---------------------------------------------
__device__ __forceinline__ float leaky(float x) { return x >= 0.f ? x : 0.01f * x; }

__device__ __forceinline__ uint32_t smem_u32(const void* p) {
    uint32_t a;
    asm("{ .reg .u64 t; cvta.to.shared.u64 t, %1; cvt.u32.u64 %0, t; }" : "=r"(a) : "l"(p));
    return a;
}

__device__ __forceinline__ void cp16(uint32_t s, const void* g) {
    asm volatile("cp.async.cg.shared.global [%0], [%1], 16;\n" :: "r"(s), "l"(g));
}

__device__ __forceinline__ void ldm_x4(uint32_t r[4], uint32_t addr) {
    asm volatile("ldmatrix.sync.aligned.m8n8.x4.shared.b16 {%0,%1,%2,%3}, [%4];"
                 : "=r"(r[0]), "=r"(r[1]), "=r"(r[2]), "=r"(r[3]) : "r"(addr));
}

__device__ __forceinline__ void mma_fp8(float c[4], const uint32_t a[4], const uint32_t b[2]) {
    asm volatile(
        "mma.sync.aligned.m16n8k32.row.col.f32.e4m3.e4m3.f32 "
        "{%0,%1,%2,%3},{%4,%5,%6,%7},{%8,%9},{%0,%1,%2,%3};\n"
        : "+f"(c[0]), "+f"(c[1]), "+f"(c[2]), "+f"(c[3])
        : "r"(a[0]), "r"(a[1]), "r"(a[2]), "r"(a[3]), "r"(b[0]), "r"(b[1]));
}

// 2 floats -> packed e4m3x2 (low byte = lo)
__device__ __forceinline__ uint16_t f2_to_e4m3x2(float hi, float lo) {
    uint16_t r;
    asm("cvt.rn.satfinite.e4m3x2.f32 %0, %1, %2;" : "=h"(r) : "f"(hi), "f"(lo));
    return r;
}

// packed e4m3x2 -> half2 (exact widening)
__device__ __forceinline__ __half2 e4m3x2_to_h2(uint16_t v) {
    uint32_t r;
    asm("cvt.rn.f16x2.e4m3x2 %0, %1;" : "=r"(r) : "h"(v));
    return *(__half2*)&r;
}

// ---------------- graph-structure kernels -----------------------------------
__global__ void deg_kernel(const int* __restrict__ ei1, const int* __restrict__ ei2) {
    int idx = blockIdx.x * blockDim.x + threadIdx.x;
    if (idx >= NB * NEDGE) return;
    int bb = idx / NEDGE, e = idx - bb * NEDGE;
    const int* ei = (bb < 8) ? ei1 + (size_t)bb * 2 * NEDGE
                             : ei2 + (size_t)(bb - 8) * 2 * NEDGE;
    int t = ei[NEDGE + e];
    atomicAdd(&g_degi[bb * NNODE + t], 1);
}

// Exclusive scan of edge-degree per graph -> CSR row offsets; also dinv.
__global__ void __launch_bounds__(1024) scan_kernel() {
    const int bb = blockIdx.x;
    const int tid = threadIdx.x;
    const int i0 = 2 * tid, i1 = 2 * tid + 1;
    int a0 = (i0 < NNODE) ? g_degi[bb * NNODE + i0] : 0;
    int a1 = (i1 < NNODE) ? g_degi[bb * NNODE + i1] : 0;
    if (i0 < NNODE) g_dinv[bb * NNODE + i0] = rsqrtf((float)(a0 + 1));
    if (i1 < NNODE) g_dinv[bb * NNODE + i1] = rsqrtf((float)(a1 + 1));
    int s = a0 + a1;

    const int lane = tid & 31, wid = tid >> 5;
    int v = s;
#pragma unroll
    for (int off = 1; off < 32; off <<= 1) {
        int u = __shfl_up_sync(0xffffffffu, v, off);
        if (lane >= off) v += u;
    }
    __shared__ int wsum[32];
    if (lane == 31) wsum[wid] = v;
    __syncthreads();
    if (wid == 0) {
        int w = wsum[lane];
#pragma unroll
        for (int off = 1; off < 32; off <<= 1) {
            int u = __shfl_up_sync(0xffffffffu, w, off);
            if (lane >= off) w += u;
        }
        wsum[lane] = w;
    }
    __syncthreads();
    int base = (wid > 0) ? wsum[wid - 1] : 0;
    int excl = base + v - s;
    g_rowptr[bb * NPAD + i0] = excl;
    g_rowptr[bb * NPAD + i1] = excl + a0;
}

__global__ void fill_kernel(const int* __restrict__ ei1, const int* __restrict__ ei2) {
    int idx = blockIdx.x * blockDim.x + threadIdx.x;
    if (idx >= NB * NEDGE) return;
    int bb = idx / NEDGE, e = idx - bb * NEDGE;
    const int* ei = (bb < 8) ? ei1 + (size_t)bb * 2 * NEDGE
                             : ei2 + (size_t)(bb - 8) * 2 * NEDGE;
    int s = ei[e];
    int t = ei[NEDGE + e];
    int slot = g_rowptr[bb * NPAD + t] + atomicAdd(&g_cur[bb * NNODE + t], 1);
    g_csr_src[bb * NEDGE + slot] = s;
    g_csr_w  [bb * NEDGE + slot] = g_dinv[bb * NNODE + s] * g_dinv[bb * NNODE + t];
}

// ---------------- conversions ------------------------------------------------
// Thread converts 8 consecutive floats -> 8 e4m3 bytes.
__global__ void convert_x_kernel(const float* __restrict__ x1, const float* __restrict__ x2) {
    size_t i = (size_t)blockIdx.x * blockDim.x + threadIdx.x;   // oct index
    const size_t total = (size_t)NB * NPAD * (FDIM / 8);
    if (i >= total) return;
    int q   = (int)(i % (FDIM / 8));
    size_t r = i / (FDIM / 8);
    int node = (int)(r % NPAD);
    int bb   = (int)(r / NPAD);
    float4 v0 = make_float4(0.f, 0.f, 0.f, 0.f), v1 = v0;
    if (node < NNODE) {
        const float* x = (bb < 8) ? x1 + ((size_t)bb * NNODE + node) * FDIM
                                  : x2 + ((size_t)(bb - 8) * NNODE + node) * FDIM;
        v0 = *(const float4*)(x + q * 8);
        v1 = *(const float4*)(x + q * 8 + 4);
    }
    uint32_t lo = (uint32_t)f2_to_e4m3x2(v0.y, v0.x)
                | ((uint32_t)f2_to_e4m3x2(v0.w, v0.z) << 16);
    uint32_t hi = (uint32_t)f2_to_e4m3x2(v1.y, v1.x)
                | ((uint32_t)f2_to_e4m3x2(v1.w, v1.z) << 16);
    uint2 o; o.x = lo; o.y = hi;
    *(uint2*)(g_Xq + ((size_t)bb * NPAD + node) * FDIM + q * 8) = o;
}

// Wq[br][o][i..i+1] = e4m3(Wg[i][o] * 16)  (pairs along K)
__global__ void wt_kernel(const float* __restrict__ Wg1, const float* __restrict__ Wg2) {
    int idx = blockIdx.x * blockDim.x + threadIdx.x;   // pair index
    if (idx >= FDIM * FDIM) return;                    // 1M pairs (2 branches x 512K)
    int br = idx >> 19;
    int j = idx & ((1 << 19) - 1);
    int o = j >> 9, ip = (j & 511) * 2;
    const float* W = br ? Wg2 : Wg1;
    float w0 = W[ip * FDIM + o] * WSCALE;
    float w1 = W[(ip + 1) * FDIM + o] * WSCALE;
    *(uint16_t*)(g_Wq + ((size_t)br << 20) + o * FDIM + ip) = f2_to_e4m3x2(w1, w0);
}

// ---------------- e4m3 mma.sync GEMM: H = X @ Wg (node-major e4m3 out) -------
// M=2048 (nodes), N=1024 (fout), K=1024. CTA tile 128x256, warp tile 64x64.
// 3-stage cp.async, one __syncthreads per K-tile.
__global__ void __launch_bounds__(256, 1) gemm_h(void)
{
    constexpr int BM = 128, BN = 256, BKB = 64, BKPB = 80;
    constexpr int NKT = FDIM / BKB;                // 16
    constexpr int STGA = BM * BKPB;                // 10240 B
    constexpr int STGB = BN * BKPB;                // 20480 B

    extern __shared__ __align__(16) uint8_t dsm[];
    uint8_t* Asm = dsm;                  // [3][128][80]
    uint8_t* Bsm = dsm + 3 * STGA;       // [3][256][80]

    const int tid = threadIdx.x;
    const int lane = tid & 31, warp = tid >> 5;
    const int wm = warp & 1, wn = warp >> 1;       // 2x4 -> warp tile 64x64
    const int g = lane >> 2, tg = lane & 3;

    const int bb   = blockIdx.z;
    const int row0 = blockIdx.y * BM;              // node offset
    const int col0 = blockIdx.x * BN;              // fout offset

    const uint8_t* Aq = g_Xq + (size_t)bb * NPAD * FDIM;
    const uint8_t* Bq = g_Wq + ((size_t)(bb < 8 ? 0 : 1) << 20);

    float acc[4][8][4];
#pragma unroll
    for (int i = 0; i < 4; i++)
#pragma unroll
        for (int j = 0; j < 8; j++)
#pragma unroll
            for (int r = 0; r < 4; r++) acc[i][j][r] = 0.f;

    auto load_tile = [&](int kt, int p) {
        const int k0 = kt * BKB;
        // A: 128 rows x 64 B = 512 cp16 (2/thread)
#pragma unroll
        for (int i = 0; i < 2; i++) {
            int u = tid + i * 256, r = u >> 2, un = u & 3;
            cp16(smem_u32(Asm + p * STGA + r * BKPB + un * 16),
                 Aq + (size_t)(row0 + r) * FDIM + k0 + un * 16);
        }
        // B: 256 rows x 64 B = 1024 cp16 (4/thread)
#pragma unroll
        for (int i = 0; i < 4; i++) {
            int u = tid + i * 256, r = u >> 2, un = u & 3;
            cp16(smem_u32(Bsm + p * STGB + r * BKPB + un * 16),
                 Bq + (size_t)(col0 + r) * FDIM + k0 + un * 16);
        }
    };

    // ldmatrix lane address components (byte offsets)
    const int a_row = (lane & 7) + ((lane >> 3) & 1) * 8;
    const int a_kb  = ((lane >> 4) & 1) * 16;
    const int b_n   = (lane & 7) + ((lane >> 4) & 1) * 8;
    const int b_kb  = ((lane >> 3) & 1) * 16;

    load_tile(0, 0);
    asm volatile("cp.async.commit_group;");
    load_tile(1, 1);
    asm volatile("cp.async.commit_group;");

#pragma unroll 1
    for (int kt = 0; kt < NKT; kt++) {
        const int p = kt % 3;
        asm volatile("cp.async.wait_group 1;");      // tile kt resident
        __syncthreads();                              // all warps done with tile kt-1
        if (kt + 2 < NKT) load_tile(kt + 2, (kt + 2) % 3);
        asm volatile("cp.async.commit_group;");      // uniform group count

#pragma unroll
        for (int ks = 0; ks < 2; ks++) {             // 2 x k32 per 64B tile
            uint32_t a[4][4], b[8][2];
#pragma unroll
            for (int mf = 0; mf < 4; mf++)
                ldm_x4(a[mf], smem_u32(Asm + p * STGA
                        + (wm * 64 + mf * 16 + a_row) * BKPB + ks * 32 + a_kb));
#pragma unroll
            for (int nfp = 0; nfp < 4; nfp++) {
                uint32_t r4[4];
                ldm_x4(r4, smem_u32(Bsm + p * STGB
                        + (wn * 64 + nfp * 16 + b_n) * BKPB + ks * 32 + b_kb));
                b[2 * nfp][0] = r4[0]; b[2 * nfp][1] = r4[1];
                b[2 * nfp + 1][0] = r4[2]; b[2 * nfp + 1][1] = r4[3];
            }
#pragma unroll
            for (int mf = 0; mf < 4; mf++)
#pragma unroll
                for (int nf = 0; nf < 8; nf++)
                    mma_fp8(acc[mf][nf], a[mf], b[nf]);
        }
    }

    // epilogue: undo WSCALE, store e4m3 H node-major (pairs of columns)
    constexpr float INV = 1.0f / WSCALE;
    uint8_t* dst = g_H + (size_t)bb * NPAD * FDIM;
#pragma unroll
    for (int mf = 0; mf < 4; mf++)
#pragma unroll
        for (int rh = 0; rh < 2; rh++) {
            int row = row0 + wm * 64 + mf * 16 + g + rh * 8;       // node
#pragma unroll
            for (int nf = 0; nf < 8; nf++) {
                int col = col0 + wn * 64 + nf * 8 + 2 * tg;         // fout (pair base)
                uint16_t hq = f2_to_e4m3x2(acc[mf][nf][rh * 2 + 1] * INV,
                                           acc[mf][nf][rh * 2] * INV);
                *(uint16_t*)(dst + (size_t)row * FDIM + col) = hq;
            }
        }
}

#define GEMM_SMEM (3 * (128 * 80 + 256 * 80))   // 92160 B

// ---------------- fused SpMM + bias + leaky + mean (fp8 gather) --------------
// 256 threads = 4 groups of 64; group handles 4 nodes; thread owns 16 features.
__global__ void __launch_bounds__(256) spmm_mean_kernel(const float* __restrict__ bg1,
                                                        const float* __restrict__ bg2)
{
    __shared__ float red[3][FDIM];     // 12 KB: partials of groups 1..3

    const int bb  = blockIdx.y;
    const int grp = threadIdx.x >> 6;          // 0..3
    const int lt  = threadIdx.x & 63;
    const int node0 = blockIdx.x * 16 + grp * 4;
    const int f0 = lt * 16;

    const float* bias = (bb < 8) ? bg1 : bg2;
    float bv[16];
#pragma unroll
    for (int i = 0; i < 4; i++) {
        float4 t = __ldg((const float4*)(bias + f0 + 4 * i));
        bv[4 * i] = t.x; bv[4 * i + 1] = t.y; bv[4 * i + 2] = t.z; bv[4 * i + 3] = t.w;
    }

    const uint8_t* H = g_H + (size_t)bb * NPAD * FDIM;
    const int* __restrict__ rp   = g_rowptr + bb * NPAD;
    const int* __restrict__ csrc = g_csr_src + bb * NEDGE;
    const float* __restrict__ cw = g_csr_w + bb * NEDGE;

    float s[16];
#pragma unroll
    for (int i = 0; i < 16; i++) s[i] = 0.f;

#pragma unroll 1
    for (int j = 0; j < 4; j++) {
        const int t = node0 + j;
        __half2 acc[8];
        {   // self loop: dinv(t)^2 * h[t]
            float ds = g_dinv[bb * NNODE + t];
            __half2 wh = __float2half2_rn(ds * ds);
            uint4 hv = __ldg((const uint4*)(H + (size_t)t * FDIM + f0));
            const uint32_t* u = (const uint32_t*)&hv;
#pragma unroll
            for (int i = 0; i < 4; i++) {
                acc[2 * i]     = __hmul2(wh, e4m3x2_to_h2((uint16_t)u[i]));
                acc[2 * i + 1] = __hmul2(wh, e4m3x2_to_h2((uint16_t)(u[i] >> 16)));
            }
        }
        const int beg = rp[t], end = rp[t + 1];
#pragma unroll 2
        for (int e = beg; e < end; e++) {
            int sn = __ldg(&csrc[e]);
            __half2 wh = __float2half2_rn(__ldg(&cw[e]));
            uint4 hv = __ldg((const uint4*)(H + (size_t)sn * FDIM + f0));
            const uint32_t* u = (const uint32_t*)&hv;
#pragma unroll
            for (int i = 0; i < 4; i++) {
                acc[2 * i]     = __hfma2(wh, e4m3x2_to_h2((uint16_t)u[i]), acc[2 * i]);
                acc[2 * i + 1] = __hfma2(wh, e4m3x2_to_h2((uint16_t)(u[i] >> 16)), acc[2 * i + 1]);
            }
        }
#pragma unroll
        for (int i = 0; i < 8; i++) {
            float2 v = __half22float2(acc[i]);
            s[2 * i]     += leaky(v.x + bv[2 * i]);
            s[2 * i + 1] += leaky(v.y + bv[2 * i + 1]);
        }
    }

    // cross-group reduction in smem, then one atomic per feature
    if (grp > 0) {
#pragma unroll
        for (int i = 0; i < 16; i++) red[grp - 1][f0 + i] = s[i];
    }
    __syncthreads();
    if (grp == 0) {
        const float sc = 1.0f / NNODE;
        float* gm = g_gmean + bb * FDIM;
#pragma unroll
        for (int i = 0; i < 16; i++)
            atomicAdd(&gm[f0 + i],
                      (s[i] + red[0][f0 + i] + red[1][f0 + i] + red[2][f0 + i]) * sc);
    }
}

// ---------------- FC (g @ Wf + bf, leaky) ------------------------------------
// grid NB, block 512: d = tid&127, f-chunk = tid>>7 (4 chunks of 256)
__global__ void __launch_bounds__(512) fc_kernel(const float* __restrict__ Wf1,
                                                 const float* __restrict__ bf1,
                                                 const float* __restrict__ Wf2,
                                                 const float* __restrict__ bf2)
{
    __shared__ float part[4][DDIM];
    int bb = blockIdx.x;
    int d = threadIdx.x & 127, c = threadIdx.x >> 7;
    const float* Wf = (bb < 8) ? Wf1 : Wf2;
    const float* bf = (bb < 8) ? bf1 : bf2;
    const float* gv = g_gmean + bb * FDIM;
    float acc = 0.f;
    const int fbeg = c * 256;
#pragma unroll 8
    for (int f = fbeg; f < fbeg + 256; f++)
        acc += gv[f] * Wf[f * DDIM + d];
    part[c][d] = acc;
    __syncthreads();
    if (c == 0)
        g_gf[bb * DDIM + d] = leaky(part[0][d] + part[1][d] + part[2][d] + part[3][d] + bf[d]);
}

// ---------------- MLP head ---------------------------------------------------
__global__ void head_kernel(const float* __restrict__ W1, const float* __restrict__ b1,
                            const float* __restrict__ W2, const float* __restrict__ b2,
                            const float* __restrict__ Wo, const float* __restrict__ bo,
                            float* __restrict__ out)
{
    __shared__ float xc[8][256];
    __shared__ float l1s[8][256];
    __shared__ float l2s[8][64];
    int tid = threadIdx.x;

    for (int i = tid; i < 8 * 256; i += 256) {
        int b = i / 256, j = i % 256;
        xc[b][j] = (j < 128) ? g_gf[b * DDIM + j] : g_gf[(8 + b) * DDIM + (j - 128)];
    }
    __syncthreads();

    for (int i = tid; i < 8 * 256; i += 256) {
        int b = i / 256, j = i % 256;
        float a = b1[j];
#pragma unroll 8
        for (int k = 0; k < 256; k++) a += xc[b][k] * W1[k * 256 + j];
        l1s[b][j] = leaky(a);
    }
    __syncthreads();

    for (int i = tid; i < 8 * 64; i += 256) {
        int b = i / 64, j = i % 64;
        float a = b2[j];
#pragma unroll 8
        for (int k = 0; k < 256; k++) a += l1s[b][k] * W2[k * 64 + j];
        l2s[b][j] = leaky(a);
    }
    __syncthreads();

    if (tid < 8) {
        float a = bo[0];
#pragma unroll
        for (int k = 0; k < 64; k++) a += l2s[tid][k] * Wo[k];
        out[tid] = 1.f / (1.f + expf(-a));
    }
}

// ---------------- launch ------------------------------------------------------
extern "C" void kernel_launch(void* const* d_in, const int* in_sizes, int n_in,
                              void* d_out, int out_size)
{
    const float* x1  = (const float*)d_in[0];
    const int*   ei1 = (const int*)d_in[1];
    const float* x2  = (const float*)d_in[2];
    const int*   ei2 = (const int*)d_in[3];
    const float* Wg1 = (const float*)d_in[4];
    const float* bg1 = (const float*)d_in[5];
    const float* Wf1 = (const float*)d_in[6];
    const float* bf1 = (const float*)d_in[7];
    const float* Wg2 = (const float*)d_in[8];
    const float* bg2 = (const float*)d_in[9];
    const float* Wf2 = (const float*)d_in[10];
    const float* bf2 = (const float*)d_in[11];
    const float* W1  = (const float*)d_in[12];
    const float* b1  = (const float*)d_in[13];
    const float* W2  = (const float*)d_in[14];
    const float* b2  = (const float*)d_in[15];
    const float* Wo  = (const float*)d_in[16];
    const float* bo  = (const float*)d_in[17];
    float* out = (float*)d_out;

    cudaFuncSetAttribute(gemm_h, cudaFuncAttributeMaxDynamicSharedMemorySize, GEMM_SMEM);

    void *pg = nullptr, *pc = nullptr, *pd = nullptr;
    cudaGetSymbolAddress(&pg, g_gmean);
    cudaGetSymbolAddress(&pc, g_cur);
    cudaGetSymbolAddress(&pd, g_degi);
    cudaMemsetAsync(pg, 0, sizeof(float) * NB * FDIM, 0);
    cudaMemsetAsync(pc, 0, sizeof(int) * NB * NNODE, 0);
    cudaMemsetAsync(pd, 0, sizeof(int) * NB * NNODE, 0);

    // graph structure -> CSR
    deg_kernel<<<(NB * NEDGE + 255) / 256, 256>>>(ei1, ei2);
    scan_kernel<<<NB, 1024>>>();
    fill_kernel<<<(NB * NEDGE + 255) / 256, 256>>>(ei1, ei2);

    // conversions (fp8)
    {
        size_t q = (size_t)NB * NPAD * (FDIM / 8);
        convert_x_kernel<<<(unsigned)((q + 255) / 256), 256>>>(x1, x2);
        wt_kernel<<<(FDIM * FDIM + 255) / 256, 256>>>(Wg1, Wg2);
    }

    // Stage 1: H = X @ Wg (fp8 mma, node-major e4m3 out), 128x256 CTA tile
    gemm_h<<<dim3(FDIM / 256, NPAD / 128, NB), 256, GEMM_SMEM>>>();

    // Stage 2: fused SpMM + bias + leaky + mean (fp8 gather, half2 fma)
    spmm_mean_kernel<<<dim3(NNODE / 16, NB), 256>>>(bg1, bg2);

    fc_kernel<<<NB, 512>>>(Wf1, bf1, Wf2, bf2);
    head_kernel<<<1, 256>>>(W1, b1, W2, b2, Wo, bo, out);
}

// round 13
// speedup vs baseline: 1.5052x; 1.5052x over previous
#include <cuda_runtime.h>
#include <cuda_bf16.h>
#include <cuda_fp16.h>
#include <math.h>
#include <stdint.h>

// Problem constants (GCNN_85409719648958): B=8, N=2000, E=64000, F=1024, D=128
#define NB     16      // 2 branches x 8 batches
#define NNODE  2000
#define NPAD   2048    // padded node count
#define NEDGE  64000
#define FDIM   1024
#define DDIM   128

#define WSCALE 16.0f   // W pre-scale for e4m3 (avoids subnormals); undone in epilogue

// ---------------- scratch (device globals; no runtime allocation) ----------
__device__ uint8_t g_Xq [(size_t)NB * NPAD * FDIM];   // 32 MB X in e4m3 (padded rows zero)
__device__ uint8_t g_Wq [(size_t)2 * FDIM * FDIM];    // 2 MB  (Wg^T * 16) in e4m3, K-major
__device__ uint8_t g_H  [(size_t)NB * NPAD * FDIM];   // 32 MB H = X@Wg, node-major e4m3
__device__ int   g_degi[NB * NNODE];                  // edge in-degree (no self loop)
__device__ float g_dinv[NB * NNODE];
__device__ int   g_rowptr[NB * NPAD];                 // CSR row offsets (by target)
__device__ int   g_cur[NB * NNODE];                   // fill cursors
__device__ int   g_csr_src[NB * NEDGE];
__device__ float g_csr_w  [NB * NEDGE];
__device__ float g_gmean[NB * FDIM];                  // mean_n leaky(A@H + b)
__device__ float g_gf[NB * DDIM];                     // leaky(g @ Wf + bf)

// ---------------- small helpers ---------------------------------------------
__device__ __forceinline__ float leaky(float x) { return x >= 0.f ? x : 0.01f * x; }

__device__ __forceinline__ uint32_t smem_u32(const void* p) {
    uint32_t a;
    asm("{ .reg .u64 t; cvta.to.shared.u64 t, %1; cvt.u32.u64 %0, t; }" : "=r"(a) : "l"(p));
    return a;
}

__device__ __forceinline__ void cp16(uint32_t s, const void* g) {
    asm volatile("cp.async.cg.shared.global [%0], [%1], 16;\n" :: "r"(s), "l"(g));
}

__device__ __forceinline__ void ldm_x4(uint32_t r[4], uint32_t addr) {
    asm volatile("ldmatrix.sync.aligned.m8n8.x4.shared.b16 {%0,%1,%2,%3}, [%4];"
                 : "=r"(r[0]), "=r"(r[1]), "=r"(r[2]), "=r"(r[3]) : "r"(addr));
}

__device__ __forceinline__ void mma_fp8(float c[4], const uint32_t a[4], const uint32_t b[2]) {
    asm volatile(
        "mma.sync.aligned.m16n8k32.row.col.f32.e4m3.e4m3.f32 "
        "{%0,%1,%2,%3},{%4,%5,%6,%7},{%8,%9},{%0,%1,%2,%3};\n"
        : "+f"(c[0]), "+f"(c[1]), "+f"(c[2]), "+f"(c[3])
        : "r"(a[0]), "r"(a[1]), "r"(a[2]), "r"(a[3]), "r"(b[0]), "r"(b[1]));
}

// 2 floats -> packed e4m3x2 (low byte = lo)
__device__ __forceinline__ uint16_t f2_to_e4m3x2(float hi, float lo) {
    uint16_t r;
    asm("cvt.rn.satfinite.e4m3x2.f32 %0, %1, %2;" : "=h"(r) : "f"(hi), "f"(lo));
    return r;
}

// packed e4m3x2 -> half2 (exact widening)
__device__ __forceinline__ __half2 e4m3x2_to_h2(uint16_t v) {
    uint32_t r;
    asm("cvt.rn.f16x2.e4m3x2 %0, %1;" : "=r"(r) : "h"(v));
    return *(__half2*)&r;
}

// ---------------- graph-structure kernels -----------------------------------
__global__ void deg_kernel(const int* __restrict__ ei1, const int* __restrict__ ei2) {
    int idx = blockIdx.x * blockDim.x + threadIdx.x;
    if (idx >= NB * NEDGE) return;
    int bb = idx / NEDGE, e = idx - bb * NEDGE;
    const int* ei = (bb < 8) ? ei1 + (size_t)bb * 2 * NEDGE
                             : ei2 + (size_t)(bb - 8) * 2 * NEDGE;
    int t = ei[NEDGE + e];
    atomicAdd(&g_degi[bb * NNODE + t], 1);
}

// Exclusive scan of edge-degree per graph -> CSR row offsets; also dinv.
__global__ void __launch_bounds__(1024) scan_kernel() {
    const int bb = blockIdx.x;
    const int tid = threadIdx.x;
    const int i0 = 2 * tid, i1 = 2 * tid + 1;
    int a0 = (i0 < NNODE) ? g_degi[bb * NNODE + i0] : 0;
    int a1 = (i1 < NNODE) ? g_degi[bb * NNODE + i1] : 0;
    if (i0 < NNODE) g_dinv[bb * NNODE + i0] = rsqrtf((float)(a0 + 1));
    if (i1 < NNODE) g_dinv[bb * NNODE + i1] = rsqrtf((float)(a1 + 1));
    int s = a0 + a1;

    const int lane = tid & 31, wid = tid >> 5;
    int v = s;
#pragma unroll
    for (int off = 1; off < 32; off <<= 1) {
        int u = __shfl_up_sync(0xffffffffu, v, off);
        if (lane >= off) v += u;
    }
    __shared__ int wsum[32];
    if (lane == 31) wsum[wid] = v;
    __syncthreads();
    if (wid == 0) {
        int w = wsum[lane];
#pragma unroll
        for (int off = 1; off < 32; off <<= 1) {
            int u = __shfl_up_sync(0xffffffffu, w, off);
            if (lane >= off) w += u;
        }
        wsum[lane] = w;
    }
    __syncthreads();
    int base = (wid > 0) ? wsum[wid - 1] : 0;
    int excl = base + v - s;
    g_rowptr[bb * NPAD + i0] = excl;
    g_rowptr[bb * NPAD + i1] = excl + a0;
}

__global__ void fill_kernel(const int* __restrict__ ei1, const int* __restrict__ ei2) {
    int idx = blockIdx.x * blockDim.x + threadIdx.x;
    if (idx >= NB * NEDGE) return;
    int bb = idx / NEDGE, e = idx - bb * NEDGE;
    const int* ei = (bb < 8) ? ei1 + (size_t)bb * 2 * NEDGE
                             : ei2 + (size_t)(bb - 8) * 2 * NEDGE;
    int s = ei[e];
    int t = ei[NEDGE + e];
    int slot = g_rowptr[bb * NPAD + t] + atomicAdd(&g_cur[bb * NNODE + t], 1);
    g_csr_src[bb * NEDGE + slot] = s;
    g_csr_w  [bb * NEDGE + slot] = g_dinv[bb * NNODE + s] * g_dinv[bb * NNODE + t];
}

// ---------------- conversions ------------------------------------------------
// Thread converts 8 consecutive floats -> 8 e4m3 bytes.
__global__ void convert_x_kernel(const float* __restrict__ x1, const float* __restrict__ x2) {
    size_t i = (size_t)blockIdx.x * blockDim.x + threadIdx.x;   // oct index
    const size_t total = (size_t)NB * NPAD * (FDIM / 8);
    if (i >= total) return;
    int q   = (int)(i % (FDIM / 8));
    size_t r = i / (FDIM / 8);
    int node = (int)(r % NPAD);
    int bb   = (int)(r / NPAD);
    float4 v0 = make_float4(0.f, 0.f, 0.f, 0.f), v1 = v0;
    if (node < NNODE) {
        const float* x = (bb < 8) ? x1 + ((size_t)bb * NNODE + node) * FDIM
                                  : x2 + ((size_t)(bb - 8) * NNODE + node) * FDIM;
        v0 = *(const float4*)(x + q * 8);
        v1 = *(const float4*)(x + q * 8 + 4);
    }
    uint32_t lo = (uint32_t)f2_to_e4m3x2(v0.y, v0.x)
                | ((uint32_t)f2_to_e4m3x2(v0.w, v0.z) << 16);
    uint32_t hi = (uint32_t)f2_to_e4m3x2(v1.y, v1.x)
                | ((uint32_t)f2_to_e4m3x2(v1.w, v1.z) << 16);
    uint2 o; o.x = lo; o.y = hi;
    *(uint2*)(g_Xq + ((size_t)bb * NPAD + node) * FDIM + q * 8) = o;
}

// Wq[br][o][i..i+1] = e4m3(Wg[i][o] * 16)  (pairs along K)
__global__ void wt_kernel(const float* __restrict__ Wg1, const float* __restrict__ Wg2) {
    int idx = blockIdx.x * blockDim.x + threadIdx.x;   // pair index
    if (idx >= FDIM * FDIM) return;                    // 1M pairs (2 branches x 512K)
    int br = idx >> 19;
    int j = idx & ((1 << 19) - 1);
    int o = j >> 9, ip = (j & 511) * 2;
    const float* W = br ? Wg2 : Wg1;
    float w0 = W[ip * FDIM + o] * WSCALE;
    float w1 = W[(ip + 1) * FDIM + o] * WSCALE;
    *(uint16_t*)(g_Wq + ((size_t)br << 20) + o * FDIM + ip) = f2_to_e4m3x2(w1, w0);
}

// ---------------- e4m3 mma.sync GEMM: H = X @ Wg (node-major e4m3 out) -------
// M=2048 (nodes), N=1024 (fout), K=1024. K-chunk 64 bytes, 3-stage cp.async.
// (Round-11 configuration: 128x128 CTA, 32x64 warp tile, 2 CTA/SM.)
__global__ void __launch_bounds__(256, 2) gemm_h(void)
{
    constexpr int BM = 128, BKB = 64, BKPB = 80;   // bytes; 80 = conflict-free pad
    constexpr int NKT = FDIM / BKB;                // 16
    constexpr int STG = BM * BKPB;                 // 10240 B per operand-stage

    extern __shared__ __align__(16) uint8_t dsm[];
    uint8_t* Asm = dsm;                  // [3][128][80]
    uint8_t* Bsm = dsm + 3 * STG;        // [3][128][80]

    const int tid = threadIdx.x;
    const int lane = tid & 31, warp = tid >> 5;
    const int wm = warp & 3, wn = warp >> 2;       // 4x2 -> warp tile 32x64
    const int g = lane >> 2, tg = lane & 3;

    const int bb   = blockIdx.z;
    const int row0 = blockIdx.y * BM;              // node offset
    const int col0 = blockIdx.x * BM;              // fout offset

    const uint8_t* Aq = g_Xq + (size_t)bb * NPAD * FDIM;
    const uint8_t* Bq = g_Wq + ((size_t)(bb < 8 ? 0 : 1) << 20);

    float acc[2][8][4];
#pragma unroll
    for (int i = 0; i < 2; i++)
#pragma unroll
        for (int j = 0; j < 8; j++)
#pragma unroll
            for (int r = 0; r < 4; r++) acc[i][j][r] = 0.f;

    auto load_tile = [&](int kt, int p) {
        const int k0 = kt * BKB;
#pragma unroll
        for (int i = 0; i < 2; i++) {
            int u = tid + i * 256, r = u >> 2, un = u & 3;
            cp16(smem_u32(Asm + p * STG + r * BKPB + un * 16),
                 Aq + (size_t)(row0 + r) * FDIM + k0 + un * 16);
        }
#pragma unroll
        for (int i = 0; i < 2; i++) {
            int u = tid + i * 256, r = u >> 2, un = u & 3;
            cp16(smem_u32(Bsm + p * STG + r * BKPB + un * 16),
                 Bq + (size_t)(col0 + r) * FDIM + k0 + un * 16);
        }
    };

    // ldmatrix lane address components (byte offsets within a row pair/k)
    const int a_row = (lane & 7) + ((lane >> 3) & 1) * 8;
    const int a_kb  = ((lane >> 4) & 1) * 16;
    const int b_n   = (lane & 7) + ((lane >> 4) & 1) * 8;
    const int b_kb  = ((lane >> 3) & 1) * 16;

    load_tile(0, 0);
    asm volatile("cp.async.commit_group;");
    load_tile(1, 1);
    asm volatile("cp.async.commit_group;");

#pragma unroll 1
    for (int kt = 0; kt < NKT; kt++) {
        const int p = kt % 3;
        if (kt + 2 < NKT) load_tile(kt + 2, (kt + 2) % 3);
        asm volatile("cp.async.commit_group;");      // uniform count
        asm volatile("cp.async.wait_group 2;");
        __syncthreads();

#pragma unroll
        for (int ks = 0; ks < 2; ks++) {             // 2 x k32 per 64B tile
            uint32_t a[2][4], b[8][2];
#pragma unroll
            for (int mf = 0; mf < 2; mf++)
                ldm_x4(a[mf], smem_u32(Asm + p * STG
                        + (wm * 32 + mf * 16 + a_row) * BKPB + ks * 32 + a_kb));
#pragma unroll
            for (int nfp = 0; nfp < 4; nfp++) {
                uint32_t r4[4];
                ldm_x4(r4, smem_u32(Bsm + p * STG
                        + (wn * 64 + nfp * 16 + b_n) * BKPB + ks * 32 + b_kb));
                b[2 * nfp][0] = r4[0]; b[2 * nfp][1] = r4[1];
                b[2 * nfp + 1][0] = r4[2]; b[2 * nfp + 1][1] = r4[3];
            }
#pragma unroll
            for (int mf = 0; mf < 2; mf++)
#pragma unroll
                for (int nf = 0; nf < 8; nf++)
                    mma_fp8(acc[mf][nf], a[mf], b[nf]);
        }
        __syncthreads();   // guard stage reuse by next iteration's loads
    }

    // epilogue: undo WSCALE, store e4m3 H node-major (pairs of columns)
    constexpr float INV = 1.0f / WSCALE;
    uint8_t* dst = g_H + (size_t)bb * NPAD * FDIM;
#pragma unroll
    for (int mf = 0; mf < 2; mf++)
#pragma unroll
        for (int rh = 0; rh < 2; rh++) {
            int row = row0 + wm * 32 + mf * 16 + g + rh * 8;       // node
#pragma unroll
            for (int nf = 0; nf < 8; nf++) {
                int col = col0 + wn * 64 + nf * 8 + 2 * tg;         // fout (pair base)
                uint16_t hq = f2_to_e4m3x2(acc[mf][nf][rh * 2 + 1] * INV,
                                           acc[mf][nf][rh * 2] * INV);
                *(uint16_t*)(dst + (size_t)row * FDIM + col) = hq;
            }
        }
}

#define GEMM_SMEM (2 * 3 * 128 * 80)   // 61440 B

// ---------------- fused SpMM + bias + leaky + mean (fp8 gather) --------------
// 256 threads = 4 groups of 64; group handles 4 nodes; thread owns 16 features.
__global__ void __launch_bounds__(256) spmm_mean_kernel(const float* __restrict__ bg1,
                                                        const float* __restrict__ bg2)
{
    __shared__ float red[3][FDIM];     // 12 KB: partials of groups 1..3

    const int bb  = blockIdx.y;
    const int grp = threadIdx.x >> 6;          // 0..3
    const int lt  = threadIdx.x & 63;
    const int node0 = blockIdx.x * 16 + grp * 4;
    const int f0 = lt * 16;

    const float* bias = (bb < 8) ? bg1 : bg2;
    float bv[16];
#pragma unroll
    for (int i = 0; i < 4; i++) {
        float4 t = __ldg((const float4*)(bias + f0 + 4 * i));
        bv[4 * i] = t.x; bv[4 * i + 1] = t.y; bv[4 * i + 2] = t.z; bv[4 * i + 3] = t.w;
    }

    const uint8_t* H = g_H + (size_t)bb * NPAD * FDIM;
    const int* __restrict__ rp   = g_rowptr + bb * NPAD;
    const int* __restrict__ csrc = g_csr_src + bb * NEDGE;
    const float* __restrict__ cw = g_csr_w + bb * NEDGE;

    float s[16];
#pragma unroll
    for (int i = 0; i < 16; i++) s[i] = 0.f;

#pragma unroll 1
    for (int j = 0; j < 4; j++) {
        const int t = node0 + j;
        __half2 acc[8];
        {   // self loop: dinv(t)^2 * h[t]
            float ds = g_dinv[bb * NNODE + t];
            __half2 wh = __float2half2_rn(ds * ds);
            uint4 hv = __ldg((const uint4*)(H + (size_t)t * FDIM + f0));
            const uint32_t* u = (const uint32_t*)&hv;
#pragma unroll
            for (int i = 0; i < 4; i++) {
                acc[2 * i]     = __hmul2(wh, e4m3x2_to_h2((uint16_t)u[i]));
                acc[2 * i + 1] = __hmul2(wh, e4m3x2_to_h2((uint16_t)(u[i] >> 16)));
            }
        }
        const int beg = rp[t], end = rp[t + 1];
#pragma unroll 2
        for (int e = beg; e < end; e++) {
            int sn = __ldg(&csrc[e]);
            __half2 wh = __float2half2_rn(__ldg(&cw[e]));
            uint4 hv = __ldg((const uint4*)(H + (size_t)sn * FDIM + f0));
            const uint32_t* u = (const uint32_t*)&hv;
#pragma unroll
            for (int i = 0; i < 4; i++) {
                acc[2 * i]     = __hfma2(wh, e4m3x2_to_h2((uint16_t)u[i]), acc[2 * i]);
                acc[2 * i + 1] = __hfma2(wh, e4m3x2_to_h2((uint16_t)(u[i] >> 16)), acc[2 * i + 1]);
            }
        }
#pragma unroll
        for (int i = 0; i < 8; i++) {
            float2 v = __half22float2(acc[i]);
            s[2 * i]     += leaky(v.x + bv[2 * i]);
            s[2 * i + 1] += leaky(v.y + bv[2 * i + 1]);
        }
    }

    // cross-group reduction in smem, then one atomic per feature
    if (grp > 0) {
#pragma unroll
        for (int i = 0; i < 16; i++) red[grp - 1][f0 + i] = s[i];
    }
    __syncthreads();
    if (grp == 0) {
        const float sc = 1.0f / NNODE;
        float* gm = g_gmean + bb * FDIM;
#pragma unroll
        for (int i = 0; i < 16; i++)
            atomicAdd(&gm[f0 + i],
                      (s[i] + red[0][f0 + i] + red[1][f0 + i] + red[2][f0 + i]) * sc);
    }
}

// ---------------- FC (g @ Wf + bf, leaky) ------------------------------------
// grid NB, block 512: d = tid&127, f-chunk = tid>>7 (4 chunks of 256)
__global__ void __launch_bounds__(512) fc_kernel(const float* __restrict__ Wf1,
                                                 const float* __restrict__ bf1,
                                                 const float* __restrict__ Wf2,
                                                 const float* __restrict__ bf2)
{
    __shared__ float part[4][DDIM];
    int bb = blockIdx.x;
    int d = threadIdx.x & 127, c = threadIdx.x >> 7;
    const float* Wf = (bb < 8) ? Wf1 : Wf2;
    const float* bf = (bb < 8) ? bf1 : bf2;
    const float* gv = g_gmean + bb * FDIM;
    float acc = 0.f;
    const int fbeg = c * 256;
#pragma unroll 8
    for (int f = fbeg; f < fbeg + 256; f++)
        acc += gv[f] * Wf[f * DDIM + d];
    part[c][d] = acc;
    __syncthreads();
    if (c == 0)
        g_gf[bb * DDIM + d] = leaky(part[0][d] + part[1][d] + part[2][d] + part[3][d] + bf[d]);
}

// ---------------- MLP head ---------------------------------------------------
__global__ void head_kernel(const float* __restrict__ W1, const float* __restrict__ b1,
                            const float* __restrict__ W2, const float* __restrict__ b2,
                            const float* __restrict__ Wo, const float* __restrict__ bo,
                            float* __restrict__ out)
{
    __shared__ float xc[8][256];
    __shared__ float l1s[8][256];
    __shared__ float l2s[8][64];
    int tid = threadIdx.x;

    for (int i = tid; i < 8 * 256; i += 256) {
        int b = i / 256, j = i % 256;
        xc[b][j] = (j < 128) ? g_gf[b * DDIM + j] : g_gf[(8 + b) * DDIM + (j - 128)];
    }
    __syncthreads();

    for (int i = tid; i < 8 * 256; i += 256) {
        int b = i / 256, j = i % 256;
        float a = b1[j];
#pragma unroll 8
        for (int k = 0; k < 256; k++) a += xc[b][k] * W1[k * 256 + j];
        l1s[b][j] = leaky(a);
    }
    __syncthreads();

    for (int i = tid; i < 8 * 64; i += 256) {
        int b = i / 64, j = i % 64;
        float a = b2[j];
#pragma unroll 8
        for (int k = 0; k < 256; k++) a += l1s[b][k] * W2[k * 64 + j];
        l2s[b][j] = leaky(a);
    }
    __syncthreads();

    if (tid < 8) {
        float a = bo[0];
#pragma unroll
        for (int k = 0; k < 64; k++) a += l2s[tid][k] * Wo[k];
        out[tid] = 1.f / (1.f + expf(-a));
    }
}

// ---------------- launch ------------------------------------------------------
extern "C" void kernel_launch(void* const* d_in, const int* in_sizes, int n_in,
                              void* d_out, int out_size)
{
    const float* x1  = (const float*)d_in[0];
    const int*   ei1 = (const int*)d_in[1];
    const float* x2  = (const float*)d_in[2];
    const int*   ei2 = (const int*)d_in[3];
    const float* Wg1 = (const float*)d_in[4];
    const float* bg1 = (const float*)d_in[5];
    const float* Wf1 = (const float*)d_in[6];
    const float* bf1 = (const float*)d_in[7];
    const float* Wg2 = (const float*)d_in[8];
    const float* bg2 = (const float*)d_in[9];
    const float* Wf2 = (const float*)d_in[10];
    const float* bf2 = (const float*)d_in[11];
    const float* W1  = (const float*)d_in[12];
    const float* b1  = (const float*)d_in[13];
    const float* W2  = (const float*)d_in[14];
    const float* b2  = (const float*)d_in[15];
    const float* Wo  = (const float*)d_in[16];
    const float* bo  = (const float*)d_in[17];
    float* out = (float*)d_out;

    // one-time resources (no device memory involved)
    static cudaStream_t s2;
    static cudaEvent_t evFork, evGemm;
    static bool inited = false;
    if (!inited) {
        cudaStreamCreateWithFlags(&s2, cudaStreamNonBlocking);
        cudaEventCreateWithFlags(&evFork, cudaEventDisableTiming);
        cudaEventCreateWithFlags(&evGemm, cudaEventDisableTiming);
        cudaFuncSetAttribute(gemm_h, cudaFuncAttributeMaxDynamicSharedMemorySize, GEMM_SMEM);
        inited = true;
    }

    void *pg = nullptr, *pc = nullptr, *pd = nullptr;
    cudaGetSymbolAddress(&pg, g_gmean);
    cudaGetSymbolAddress(&pc, g_cur);
    cudaGetSymbolAddress(&pd, g_degi);

    // ---- fork ----
    cudaEventRecord(evFork, 0);
    cudaStreamWaitEvent(s2, evFork, 0);

    // ---- stream s2: convert path + full GEMM (tensor-bound, big) ----
    {
        size_t q = (size_t)NB * NPAD * (FDIM / 8);
        convert_x_kernel<<<(unsigned)((q + 255) / 256), 256, 0, s2>>>(x1, x2);
        wt_kernel<<<(FDIM * FDIM + 255) / 256, 256, 0, s2>>>(Wg1, Wg2);
        gemm_h<<<dim3(FDIM / 128, NPAD / 128, NB), 256, GEMM_SMEM, s2>>>();
        cudaEventRecord(evGemm, s2);
    }

    // ---- stream 0: CSR build (tiny, atomics; hides under the GEMM) ----
    cudaMemsetAsync(pg, 0, sizeof(float) * NB * FDIM, 0);
    cudaMemsetAsync(pc, 0, sizeof(int) * NB * NNODE, 0);
    cudaMemsetAsync(pd, 0, sizeof(int) * NB * NNODE, 0);
    deg_kernel<<<(NB * NEDGE + 255) / 256, 256>>>(ei1, ei2);
    scan_kernel<<<NB, 1024>>>();
    fill_kernel<<<(NB * NEDGE + 255) / 256, 256>>>(ei1, ei2);

    // ---- join: spmm needs CSR (stream 0) and H (s2) ----
    cudaStreamWaitEvent(0, evGemm, 0);
    spmm_mean_kernel<<<dim3(NNODE / 16, NB), 256>>>(bg1, bg2);

    fc_kernel<<<NB, 512>>>(Wf1, bf1, Wf2, bf2);
    head_kernel<<<1, 256>>>(W1, b1, W2, b2, Wo, bo, out);
}